// round 16
// baseline (speedup 1.0000x reference)
#include <cuda_runtime.h>
#include <cstdint>

// x: (B=8, H=256, W=256, C=64) fp32, WIN=16, half=8
// out: (B, 961, 16*16*64) fp32, partition order (0,0),(0,8),(8,0),(8,8)
// windows per partition: 256, 240, 240, 225 -> 961 per batch
//
// R15 skeleton (best: 94.688us; DRAM pinned at 6.36TB/s across ALL variants)
// with ONE change: st.global.wt stores (write-through, no L2 retention).
// Hypothesis: the 504MB write stream's L2 allocations evict the ~134MB input
// between graph replays, causing the residual ~74MB of DRAM reads. Writes
// that pass through without retention leave L2 to the input -> reads ~0,
// DRAM traffic 578 -> ~515MB.

#define Hh 256
#define Ww 256
#define Cc 64
#define NPB 961                // windows per batch
#define ROW_F4 (Ww * Cc / 4)   // float4 per input image row = 4096

__global__ void __launch_bounds__(128, 3)
partition_kernel(const float* __restrict__ x, float* __restrict__ out)
{
    const int blk = blockIdx.x;            // b * 961 + p
    const int b   = blk / NPB;
    const int p   = blk - b * NPB;

    int r0, c0, nc, base;
    if (p < 256)      { r0 = 0; c0 = 0; nc = 16; base = 0;   }
    else if (p < 496) { r0 = 0; c0 = 8; nc = 15; base = 256; }
    else if (p < 736) { r0 = 8; c0 = 0; nc = 16; base = 496; }
    else              { r0 = 8; c0 = 8; nc = 15; base = 736; }

    const int q  = p - base;
    const int wr = q / nc;
    const int wc = q - wr * nc;
    const int row0 = r0 + wr * 16;
    const int col0 = c0 + wc * 16;

    const float4* __restrict__ src =
        reinterpret_cast<const float4*>(x) +
        (size_t)(b * Hh + row0) * ROW_F4 + (size_t)col0 * (Cc / 4);
    float4* __restrict__ dst =
        reinterpret_cast<float4*>(out) + (size_t)blk * (16 * 16 * Cc / 4);

    const int t = threadIdx.x;             // 0..127

    // 32 independent 128-bit loads per thread (rows i, float4 {t, t+128}).
    float4 v[32];
#pragma unroll
    for (int i = 0; i < 16; ++i) {
        v[2 * i]     = __ldg(&src[(size_t)i * ROW_F4 + t]);
        v[2 * i + 1] = __ldg(&src[(size_t)i * ROW_F4 + t + 128]);
    }

    // Write-through stores: no L2 line retention for the output stream.
#pragma unroll
    for (int i = 0; i < 16; ++i) {
        const float4 a = v[2 * i];
        const float4 c = v[2 * i + 1];
        float4* g0 = &dst[i * 256 + t];
        float4* g1 = &dst[i * 256 + t + 128];
        asm volatile("st.global.wt.v4.f32 [%0], {%1,%2,%3,%4};"
                     :: "l"(g0), "f"(a.x), "f"(a.y), "f"(a.z), "f"(a.w)
                     : "memory");
        asm volatile("st.global.wt.v4.f32 [%0], {%1,%2,%3,%4};"
                     :: "l"(g1), "f"(c.x), "f"(c.y), "f"(c.z), "f"(c.w)
                     : "memory");
    }
}

extern "C" void kernel_launch(void* const* d_in, const int* in_sizes, int n_in,
                              void* d_out, int out_size)
{
    const float* x = (const float*)d_in[0];
    float* out = (float*)d_out;
    const int nblocks = 8 * NPB;           // 7688
    partition_kernel<<<nblocks, 128>>>(x, out);
}

// round 17
// speedup vs baseline: 1.0323x; 1.0323x over previous
#include <cuda_runtime.h>
#include <cstdint>

// FINAL — converged after 16 rounds of A/B on every structural axis.
//
// x: (B=8, H=256, W=256, C=64) fp32, WIN=16, half=8
// out: (B, 961, 16*16*64) fp32, partition order (0,0),(0,8),(8,0),(8,8)
// windows per partition: 256, 240, 240, 225 -> 961 per batch
//
// One CTA per window (7688 one-shot blocks; persistent variants lose ~25%
// by destroying load/store phase diversity). 128 threads, each owning 32
// float4: all 32 independent LDG.128 front-batched (140 regs, max in-flight
// read bytes), then 32 STG.128.cs (evict-first streaming stores: -3.4us vs
// default, -3.6us vs .wt — pollution control for the L2-resident input).
// DRAM is pinned at ~6.36TB/s effective (80% of 8TB/s spec) on ~578MB of
// traffic (504MB irreducible writes + ~74MB residual reads after cross-
// replay L2 retention) — the hard ceiling for this write-dominated mix.
// Measured: 94.7us, rel_err 0.

#define Hh 256
#define Ww 256
#define Cc 64
#define NPB 961                // windows per batch
#define ROW_F4 (Ww * Cc / 4)   // float4 per input image row = 4096

__global__ void __launch_bounds__(128, 3)
partition_kernel(const float* __restrict__ x, float* __restrict__ out)
{
    const int blk = blockIdx.x;            // b * 961 + p
    const int b   = blk / NPB;
    const int p   = blk - b * NPB;

    int r0, c0, nc, base;
    if (p < 256)      { r0 = 0; c0 = 0; nc = 16; base = 0;   }
    else if (p < 496) { r0 = 0; c0 = 8; nc = 15; base = 256; }
    else if (p < 736) { r0 = 8; c0 = 0; nc = 16; base = 496; }
    else              { r0 = 8; c0 = 8; nc = 15; base = 736; }

    const int q  = p - base;
    const int wr = q / nc;
    const int wc = q - wr * nc;
    const int row0 = r0 + wr * 16;
    const int col0 = c0 + wc * 16;

    const float4* __restrict__ src =
        reinterpret_cast<const float4*>(x) +
        (size_t)(b * Hh + row0) * ROW_F4 + (size_t)col0 * (Cc / 4);
    float4* __restrict__ dst =
        reinterpret_cast<float4*>(out) + (size_t)blk * (16 * 16 * Cc / 4);

    const int t = threadIdx.x;             // 0..127

    // 32 independent 128-bit loads per thread: row i, float4 {t, t+128}.
    float4 v[32];
#pragma unroll
    for (int i = 0; i < 16; ++i) {
        v[2 * i]     = __ldg(&src[(size_t)i * ROW_F4 + t]);
        v[2 * i + 1] = __ldg(&src[(size_t)i * ROW_F4 + t + 128]);
    }
#pragma unroll
    for (int i = 0; i < 16; ++i) {
        __stcs(&dst[i * 256 + t],       v[2 * i]);
        __stcs(&dst[i * 256 + t + 128], v[2 * i + 1]);
    }
}

extern "C" void kernel_launch(void* const* d_in, const int* in_sizes, int n_in,
                              void* d_out, int out_size)
{
    const float* x = (const float*)d_in[0];
    float* out = (float*)d_out;
    const int nblocks = 8 * NPB;           // 7688
    partition_kernel<<<nblocks, 128>>>(x, out);
}